// round 2
// baseline (speedup 1.0000x reference)
#include <cuda_runtime.h>
#include <cuda_bf16.h>
#include <math.h>

// Problem constants
#define BB 4
#define TT 2048
#define CC 1024
#define NHH 16
#define HDD 64
#define ROWS (BB*TT)          // 8192
#define N_QKV (3*CC)          // 3072

// ---------------- scratch (device globals; no allocation) ----------------
__device__ float g_qkv[(size_t)ROWS * N_QKV];          // [8192][3072]
__device__ float g_q[(size_t)BB * NHH * TT * HDD];     // [b,h,t,d]
__device__ float g_k[(size_t)BB * NHH * TT * HDD];
__device__ float g_v[(size_t)BB * NHH * TT * HDD];
__device__ float g_y[(size_t)ROWS * CC];               // attention out, [b,t,c]

// ---------------- SGEMM: C = A[MxK] @ B[KxN] + bias[N] -------------------
// BM=BN=128, BK=16, 256 threads, 8x8 per thread. All dims divisible.
__global__ __launch_bounds__(256) void sgemm_bias_kernel(
    const float* __restrict__ A, const float* __restrict__ Bm,
    const float* __restrict__ bias, float* __restrict__ C,
    int M, int N, int K)
{
    __shared__ float sA[16][132];   // transposed A tile: sA[k][row]
    __shared__ float sB[16][128];

    const int tid = threadIdx.x;
    const int row0 = blockIdx.y * 128;
    const int col0 = blockIdx.x * 128;
    const int rowBase = (tid >> 4) << 3;   // (tid/16)*8
    const int colBase = (tid & 15) << 3;   // (tid%16)*8

    float acc[8][8];
    #pragma unroll
    for (int i = 0; i < 8; i++)
        #pragma unroll
        for (int j = 0; j < 8; j++) acc[i][j] = 0.f;

    for (int k0 = 0; k0 < K; k0 += 16) {
        // load A tile 128x16 (transposed into smem)
        #pragma unroll
        for (int r = 0; r < 2; r++) {
            int idx = tid + r * 256;           // 0..511 float4s
            int arow = idx >> 2;               // 0..127
            int akq = (idx & 3) << 2;          // 0,4,8,12
            float4 v = *(const float4*)&A[(size_t)(row0 + arow) * K + k0 + akq];
            sA[akq + 0][arow] = v.x;
            sA[akq + 1][arow] = v.y;
            sA[akq + 2][arow] = v.z;
            sA[akq + 3][arow] = v.w;
        }
        // load B tile 16x128
        #pragma unroll
        for (int r = 0; r < 2; r++) {
            int idx = tid + r * 256;
            int brow = idx >> 5;               // 0..15
            int bc = (idx & 31) << 2;          // 0..124
            *(float4*)&sB[brow][bc] =
                *(const float4*)&Bm[(size_t)(k0 + brow) * N + col0 + bc];
        }
        __syncthreads();

        #pragma unroll
        for (int k = 0; k < 16; k++) {
            float a[8], b[8];
            *(float4*)&a[0] = *(const float4*)&sA[k][rowBase];
            *(float4*)&a[4] = *(const float4*)&sA[k][rowBase + 4];
            *(float4*)&b[0] = *(const float4*)&sB[k][colBase];
            *(float4*)&b[4] = *(const float4*)&sB[k][colBase + 4];
            #pragma unroll
            for (int i = 0; i < 8; i++)
                #pragma unroll
                for (int j = 0; j < 8; j++)
                    acc[i][j] += a[i] * b[j];
        }
        __syncthreads();
    }

    // epilogue with bias
    #pragma unroll
    for (int i = 0; i < 8; i++) {
        #pragma unroll
        for (int j4 = 0; j4 < 8; j4 += 4) {
            float4 o;
            o.x = acc[i][j4 + 0] + bias[col0 + colBase + j4 + 0];
            o.y = acc[i][j4 + 1] + bias[col0 + colBase + j4 + 1];
            o.z = acc[i][j4 + 2] + bias[col0 + colBase + j4 + 2];
            o.w = acc[i][j4 + 3] + bias[col0 + colBase + j4 + 3];
            *(float4*)&C[(size_t)(row0 + rowBase + i) * N + col0 + colBase + j4] = o;
        }
    }
}

// ---------------- RoPE + head split --------------------------------------
// idx = ((b*NH + h)*T + t)*HD + d  (matches [b,h,t,d] output layout)
__global__ __launch_bounds__(256) void rope_split_kernel(
    const float* __restrict__ qkv,
    float* __restrict__ Q, float* __restrict__ Kh, float* __restrict__ V)
{
    int idx = blockIdx.x * 256 + threadIdx.x;
    int d = idx & 63;
    int t = (idx >> 6) & 2047;
    int h = (idx >> 17) & 15;
    int b = idx >> 21;

    size_t rowoff = ((size_t)b * TT + t) * N_QKV;
    int colq = h * HDD + d;

    float uq = qkv[rowoff + colq];
    float uk = qkv[rowoff + CC + colq];
    float uv = qkv[rowoff + 2 * CC + colq];

    bool hi = d >= 32;
    int i = d & 31;
    // inv_freq = 10000^(-i/32), computed in double for accuracy
    double inv = exp(-(double)i / 32.0 * 9.210340371976184);  // ln(10000)
    double fr = (double)t * inv;
    double sv, cv;
    sincos(fr, &sv, &cv);
    float cosv = (float)cv, sinv = (float)sv;

    int pcol = hi ? (colq - 32) : (colq + 32);
    float pq = qkv[rowoff + pcol];
    float pk = qkv[rowoff + CC + pcol];
    float rq = hi ? pq : -pq;
    float rk = hi ? pk : -pk;

    Q[idx] = uq * cosv + rq * sinv;
    Kh[idx] = uk * cosv + rk * sinv;
    V[idx] = uv;
}

// ---------------- Flash attention (causal, fp32) --------------------------
// BM=BN=64, HD=64, 256 threads (16x16), each thread a 4x4 tile.
#define QK_LD 72   // stride for QsT/KsT [d][row], float4-aligned
#define PV_LD 68   // stride for Vs/Ps, float4-aligned

__global__ __launch_bounds__(256) void flash_attn_kernel(
    const float* __restrict__ Qg, const float* __restrict__ Kg,
    const float* __restrict__ Vg, float* __restrict__ Yg)
{
    extern __shared__ float sm[];
    float* QsT = sm;                         // [64][QK_LD], d-major
    float* KsT = QsT + 64 * QK_LD;           // [64][QK_LD], d-major
    float* Vs  = KsT + 64 * QK_LD;           // [64][PV_LD], row-major
    float* Ps  = Vs  + 64 * PV_LD;           // [64][PV_LD]

    const int tid = threadIdx.x;
    const int ty = tid >> 4;                 // 0..15 -> 4 S rows
    const int tx = tid & 15;                 // 0..15 -> 4 S cols
    const int qtile = blockIdx.x;            // 0..31
    const int bh = blockIdx.y;               // 0..63
    const int b = bh >> 4, h = bh & 15;

    const float* Qb = Qg + ((size_t)bh * TT + qtile * 64) * HDD;

    // load Q tile transposed
    #pragma unroll
    for (int r = 0; r < 4; r++) {
        int idx = tid + r * 256;
        int trow = idx >> 4;
        int dg = (idx & 15) << 2;
        float4 v = *(const float4*)(Qb + trow * 64 + dg);
        QsT[(dg + 0) * QK_LD + trow] = v.x;
        QsT[(dg + 1) * QK_LD + trow] = v.y;
        QsT[(dg + 2) * QK_LD + trow] = v.z;
        QsT[(dg + 3) * QK_LD + trow] = v.w;
    }

    float m[4], l[4], acc[4][4];
    #pragma unroll
    for (int i = 0; i < 4; i++) {
        m[i] = -1e30f; l[i] = 0.f;
        #pragma unroll
        for (int j = 0; j < 4; j++) acc[i][j] = 0.f;
    }
    __syncthreads();

    for (int kt = 0; kt <= qtile; kt++) {
        const float* Kb = Kg + ((size_t)bh * TT + kt * 64) * HDD;
        const float* Vb = Vg + ((size_t)bh * TT + kt * 64) * HDD;
        #pragma unroll
        for (int r = 0; r < 4; r++) {
            int idx = tid + r * 256;
            int trow = idx >> 4;
            int dg = (idx & 15) << 2;
            float4 v = *(const float4*)(Kb + trow * 64 + dg);
            KsT[(dg + 0) * QK_LD + trow] = v.x;
            KsT[(dg + 1) * QK_LD + trow] = v.y;
            KsT[(dg + 2) * QK_LD + trow] = v.z;
            KsT[(dg + 3) * QK_LD + trow] = v.w;
            float4 w = *(const float4*)(Vb + trow * 64 + dg);
            *(float4*)(Vs + trow * PV_LD + dg) = w;
        }
        __syncthreads();

        // S = Q K^T
        float s[4][4];
        #pragma unroll
        for (int i = 0; i < 4; i++)
            #pragma unroll
            for (int j = 0; j < 4; j++) s[i][j] = 0.f;

        #pragma unroll 8
        for (int k = 0; k < 64; k++) {
            float4 qv = *(const float4*)(QsT + k * QK_LD + (ty << 2));
            float4 kv = *(const float4*)(KsT + k * QK_LD + (tx << 2));
            s[0][0] += qv.x * kv.x; s[0][1] += qv.x * kv.y; s[0][2] += qv.x * kv.z; s[0][3] += qv.x * kv.w;
            s[1][0] += qv.y * kv.x; s[1][1] += qv.y * kv.y; s[1][2] += qv.y * kv.z; s[1][3] += qv.y * kv.w;
            s[2][0] += qv.z * kv.x; s[2][1] += qv.z * kv.y; s[2][2] += qv.z * kv.z; s[2][3] += qv.z * kv.w;
            s[3][0] += qv.w * kv.x; s[3][1] += qv.w * kv.y; s[3][2] += qv.w * kv.z; s[3][3] += qv.w * kv.w;
        }

        // scale + causal mask (only diagonal tile needs masking)
        const float sc = 0.125f;  // 1/sqrt(64)
        if (kt == qtile) {
            #pragma unroll
            for (int i = 0; i < 4; i++)
                #pragma unroll
                for (int j = 0; j < 4; j++) {
                    int rr = (ty << 2) + i, cc = (tx << 2) + j;
                    s[i][j] = (cc <= rr) ? s[i][j] * sc : -1e30f;
                }
        } else {
            #pragma unroll
            for (int i = 0; i < 4; i++)
                #pragma unroll
                for (int j = 0; j < 4; j++) s[i][j] *= sc;
        }

        // online softmax
        #pragma unroll
        for (int i = 0; i < 4; i++) {
            float mx = fmaxf(fmaxf(s[i][0], s[i][1]), fmaxf(s[i][2], s[i][3]));
            #pragma unroll
            for (int o = 8; o > 0; o >>= 1)
                mx = fmaxf(mx, __shfl_xor_sync(0xffffffffu, mx, o));
            float mnew = fmaxf(m[i], mx);
            float alpha = __expf(m[i] - mnew);
            float rs = 0.f;
            #pragma unroll
            for (int j = 0; j < 4; j++) {
                float p = __expf(s[i][j] - mnew);
                s[i][j] = p;
                rs += p;
            }
            #pragma unroll
            for (int o = 8; o > 0; o >>= 1)
                rs += __shfl_xor_sync(0xffffffffu, rs, o);
            l[i] = l[i] * alpha + rs;
            m[i] = mnew;
            acc[i][0] *= alpha; acc[i][1] *= alpha; acc[i][2] *= alpha; acc[i][3] *= alpha;
        }

        // store P to smem
        #pragma unroll
        for (int i = 0; i < 4; i++) {
            float4 pv = make_float4(s[i][0], s[i][1], s[i][2], s[i][3]);
            *(float4*)(Ps + (((ty << 2) + i) * PV_LD) + (tx << 2)) = pv;
        }
        __syncthreads();

        // O += P @ V
        #pragma unroll 8
        for (int c = 0; c < 64; c++) {
            float4 vv = *(const float4*)(Vs + c * PV_LD + (tx << 2));
            float p0 = Ps[((ty << 2) + 0) * PV_LD + c];
            float p1 = Ps[((ty << 2) + 1) * PV_LD + c];
            float p2 = Ps[((ty << 2) + 2) * PV_LD + c];
            float p3 = Ps[((ty << 2) + 3) * PV_LD + c];
            acc[0][0] += p0 * vv.x; acc[0][1] += p0 * vv.y; acc[0][2] += p0 * vv.z; acc[0][3] += p0 * vv.w;
            acc[1][0] += p1 * vv.x; acc[1][1] += p1 * vv.y; acc[1][2] += p1 * vv.z; acc[1][3] += p1 * vv.w;
            acc[2][0] += p2 * vv.x; acc[2][1] += p2 * vv.y; acc[2][2] += p2 * vv.z; acc[2][3] += p2 * vv.w;
            acc[3][0] += p3 * vv.x; acc[3][1] += p3 * vv.y; acc[3][2] += p3 * vv.z; acc[3][3] += p3 * vv.w;
        }
        __syncthreads();
    }

    // write back to [b,t,c]
    #pragma unroll
    for (int i = 0; i < 4; i++) {
        float inv = 1.f / l[i];
        int tglob = qtile * 64 + (ty << 2) + i;
        float4 o = make_float4(acc[i][0] * inv, acc[i][1] * inv,
                               acc[i][2] * inv, acc[i][3] * inv);
        *(float4*)(Yg + ((size_t)(b * TT + tglob)) * CC + h * HDD + (tx << 2)) = o;
    }
}

// ---------------- launch ---------------------------------------------------
extern "C" void kernel_launch(void* const* d_in, const int* in_sizes, int n_in,
                              void* d_out, int out_size)
{
    const float* x     = (const float*)d_in[0];
    const float* Wqkv  = (const float*)d_in[1];
    const float* bqkv  = (const float*)d_in[2];
    const float* Wproj = (const float*)d_in[3];
    const float* bproj = (const float*)d_in[4];
    float* out = (float*)d_out;

    float *qkv, *Q, *K, *V, *Y;
    cudaGetSymbolAddress((void**)&qkv, g_qkv);
    cudaGetSymbolAddress((void**)&Q, g_q);
    cudaGetSymbolAddress((void**)&K, g_k);
    cudaGetSymbolAddress((void**)&V, g_v);
    cudaGetSymbolAddress((void**)&Y, g_y);

    // 1) QKV GEMM + bias
    sgemm_bias_kernel<<<dim3(N_QKV / 128, ROWS / 128), 256>>>(
        x, Wqkv, bqkv, qkv, ROWS, N_QKV, CC);

    // 2) RoPE + head split
    rope_split_kernel<<<(BB * NHH * TT * HDD) / 256, 256>>>(qkv, Q, K, V);

    // 3) causal flash attention
    int smem = (2 * 64 * QK_LD + 2 * 64 * PV_LD) * (int)sizeof(float);  // 71680
    cudaFuncSetAttribute(flash_attn_kernel,
                         cudaFuncAttributeMaxDynamicSharedMemorySize, smem);
    flash_attn_kernel<<<dim3(TT / 64, BB * NHH), 256, smem>>>(Q, K, V, Y);

    // 4) output projection + bias
    sgemm_bias_kernel<<<dim3(CC / 128, ROWS / 128), 256>>>(
        Y, Wproj, bproj, out, ROWS, CC, CC);
}

// round 4
// speedup vs baseline: 1.8492x; 1.8492x over previous
#include <cuda_runtime.h>
#include <cuda_bf16.h>
#include <math.h>
#include <stdint.h>

// Problem constants
#define BB 4
#define TT 2048
#define CC 1024
#define NHH 16
#define HDD 64
#define ROWS (BB*TT)          // 8192
#define N_QKV (3*CC)          // 3072

// ---------------- scratch (device globals; no allocation) ----------------
__device__ float g_qkv[(size_t)ROWS * N_QKV];
__device__ float g_q[(size_t)BB * NHH * TT * HDD];
__device__ float g_k[(size_t)BB * NHH * TT * HDD];
__device__ float g_v[(size_t)BB * NHH * TT * HDD];
__device__ float g_y[(size_t)ROWS * CC];

__device__ __nv_bfloat16 g_xh[(size_t)ROWS * CC];
__device__ __nv_bfloat16 g_xl[(size_t)ROWS * CC];
__device__ __nv_bfloat16 g_wqh[(size_t)N_QKV * CC];   // [N,K] transposed
__device__ __nv_bfloat16 g_wql[(size_t)N_QKV * CC];
__device__ __nv_bfloat16 g_wph[(size_t)CC * CC];
__device__ __nv_bfloat16 g_wpl[(size_t)CC * CC];
__device__ __nv_bfloat16 g_yh[(size_t)ROWS * CC];
__device__ __nv_bfloat16 g_yl[(size_t)ROWS * CC];
__device__ float g_cost[(size_t)TT * 32];
__device__ float g_sint[(size_t)TT * 32];

// ---------------- PTX helpers (arch-baseline only: no tcgen05!) -----------
__device__ __forceinline__ uint32_t smem_u32(const void* p) {
    uint32_t a;
    asm("{ .reg .u64 t; cvta.to.shared.u64 t, %1; cvt.u32.u64 %0, t; }" : "=r"(a) : "l"(p));
    return a;
}
__device__ __forceinline__ void cp16(uint32_t saddr, const void* g) {
    asm volatile("cp.async.cg.shared.global [%0], [%1], 16;" :: "r"(saddr), "l"(g));
}
__device__ __forceinline__ void ldsm4(uint32_t* r, uint32_t addr) {
    asm volatile("ldmatrix.sync.aligned.m8n8.x4.shared.b16 {%0,%1,%2,%3}, [%4];"
                 : "=r"(r[0]), "=r"(r[1]), "=r"(r[2]), "=r"(r[3]) : "r"(addr));
}
__device__ __forceinline__ void mma16816(float* c, const uint32_t* a, const uint32_t* b) {
    asm volatile(
        "mma.sync.aligned.m16n8k16.row.col.f32.bf16.bf16.f32 "
        "{%0,%1,%2,%3}, {%4,%5,%6,%7}, {%8,%9}, {%0,%1,%2,%3};"
        : "+f"(c[0]), "+f"(c[1]), "+f"(c[2]), "+f"(c[3])
        : "r"(a[0]), "r"(a[1]), "r"(a[2]), "r"(a[3]), "r"(b[0]), "r"(b[1]));
}

// ---------------- precision-split conversions ------------------------------
__global__ __launch_bounds__(256) void split_kernel(
    const float* __restrict__ in, __nv_bfloat16* __restrict__ hi,
    __nv_bfloat16* __restrict__ lo, int n)
{
    int i = blockIdx.x * 256 + threadIdx.x;
    if (i >= n) return;
    float v = in[i];
    __nv_bfloat16 h = __float2bfloat16(v);
    hi[i] = h;
    lo[i] = __float2bfloat16(v - __bfloat162float(h));
}

// W[K,N] f32 -> hi/lo[N,K] bf16 (transpose + split)
__global__ __launch_bounds__(256) void transpose_split_kernel(
    const float* __restrict__ W, __nv_bfloat16* __restrict__ hi,
    __nv_bfloat16* __restrict__ lo, int K, int N)
{
    __shared__ float tile[32][33];
    int k0 = blockIdx.x * 32, n0 = blockIdx.y * 32;
    int tx = threadIdx.x & 31, ty = threadIdx.x >> 5;   // 32x8
    #pragma unroll
    for (int r = 0; r < 4; r++)
        tile[ty + 8 * r][tx] = W[(size_t)(k0 + ty + 8 * r) * N + n0 + tx];
    __syncthreads();
    #pragma unroll
    for (int r = 0; r < 4; r++) {
        float v = tile[tx][ty + 8 * r];
        __nv_bfloat16 h = __float2bfloat16(v);
        size_t o = (size_t)(n0 + ty + 8 * r) * K + k0 + tx;
        hi[o] = h;
        lo[o] = __float2bfloat16(v - __bfloat162float(h));
    }
}

// ---------------- HMMA split-bf16 GEMM (mma.sync, arch-baseline) ----------
// C[M,N] = Ah@Bh^T + Ah@Bl^T + Al@Bh^T + bias ;  A:[M,K] bf16, B:[N,K] bf16
// 128x128 tile, BK=64, 256 threads (8 warps, 4x2), 2-stage cp.async pipeline.
#define TILE_B 16384           // 128 rows * 128 bytes
#define STAGE_B (4*TILE_B)     // Ah, Al, Bh, Bl
#define GSMEM (2*STAGE_B)      // 131072

__device__ __forceinline__ void load_stage(
    uint32_t base, int kt, int tid, int row0, int col0, int K,
    const __nv_bfloat16* __restrict__ Ah, const __nv_bfloat16* __restrict__ Al,
    const __nv_bfloat16* __restrict__ Bh, const __nv_bfloat16* __restrict__ Bl)
{
    int k0 = kt * 64;
    const __nv_bfloat16* srcs[4] = {Ah, Al, Bh, Bl};
    #pragma unroll
    for (int t = 0; t < 4; t++) {
        int rbase = (t < 2) ? row0 : col0;
        const __nv_bfloat16* s = srcs[t];
        #pragma unroll
        for (int i = 0; i < 4; i++) {
            int lin = i * 256 + tid;          // 0..1023
            int r = lin >> 3, c = lin & 7;
            uint32_t off = r * 128 + c * 16;
            uint32_t sw = off ^ ((off >> 3) & 0x70);
            cp16(base + t * TILE_B + sw, s + (size_t)(rbase + r) * K + k0 + c * 8);
        }
    }
    asm volatile("cp.async.commit_group;" ::: "memory");
}

__global__ __launch_bounds__(256, 1) void tc_gemm_kernel(
    const __nv_bfloat16* __restrict__ Ah, const __nv_bfloat16* __restrict__ Al,
    const __nv_bfloat16* __restrict__ Bh, const __nv_bfloat16* __restrict__ Bl,
    const float* __restrict__ bias, float* __restrict__ C, int N, int K)
{
    extern __shared__ char smem[];
    uint32_t sb = smem_u32(smem);
    const int tid = threadIdx.x;
    const int wid = tid >> 5, lane = tid & 31;
    const int wr = (wid & 3) * 32;     // warp row offset within 128
    const int wc = (wid >> 2) * 64;    // warp col offset within 128
    const int col0 = blockIdx.x * 128;
    const int row0 = blockIdx.y * 128;
    const int NK = K >> 6;

    float acc[2][8][4];
    #pragma unroll
    for (int mi = 0; mi < 2; mi++)
        #pragma unroll
        for (int ni = 0; ni < 8; ni++)
            #pragma unroll
            for (int j = 0; j < 4; j++) acc[mi][ni][j] = 0.f;

    load_stage(sb, 0, tid, row0, col0, K, Ah, Al, Bh, Bl);

    const int grp = lane >> 3, l8 = lane & 7;

    for (int kt = 0; kt < NK; kt++) {
        int s = kt & 1;
        if (kt + 1 < NK) {
            load_stage(sb + (s ^ 1) * STAGE_B, kt + 1, tid, row0, col0, K, Ah, Al, Bh, Bl);
            asm volatile("cp.async.wait_group 1;" ::: "memory");
        } else {
            asm volatile("cp.async.wait_group 0;" ::: "memory");
        }
        __syncthreads();

        uint32_t sbase = sb + s * STAGE_B;
        // passes: (Ah,Bh), (Ah,Bl), (Al,Bh)
        #pragma unroll
        for (int p = 0; p < 3; p++) {
            uint32_t abase = sbase + ((p == 2) ? TILE_B : 0);
            uint32_t bbase = sbase + ((p == 1) ? 3 * TILE_B : 2 * TILE_B);
            #pragma unroll
            for (int ks = 0; ks < 4; ks++) {
                uint32_t a[2][4], b[8][2];
                #pragma unroll
                for (int mi = 0; mi < 2; mi++) {
                    int row = wr + mi * 16 + (grp & 1) * 8 + l8;
                    int chunk = ks * 2 + (grp >> 1);
                    ldsm4(a[mi], abase + row * 128 + ((chunk ^ (row & 7)) << 4));
                }
                #pragma unroll
                for (int nj = 0; nj < 4; nj++) {
                    int row = wc + nj * 16 + (grp >> 1) * 8 + l8;
                    int chunk = ks * 2 + (grp & 1);
                    uint32_t rr[4];
                    ldsm4(rr, bbase + row * 128 + ((chunk ^ (row & 7)) << 4));
                    b[2 * nj][0] = rr[0]; b[2 * nj][1] = rr[1];
                    b[2 * nj + 1][0] = rr[2]; b[2 * nj + 1][1] = rr[3];
                }
                #pragma unroll
                for (int mi = 0; mi < 2; mi++)
                    #pragma unroll
                    for (int ni = 0; ni < 8; ni++)
                        mma16816(acc[mi][ni], a[mi], b[ni]);
            }
        }
        __syncthreads();
    }

    // epilogue with bias
    const int qr = lane >> 2, qc = (lane & 3) * 2;
    #pragma unroll
    for (int mi = 0; mi < 2; mi++) {
        #pragma unroll
        for (int ni = 0; ni < 8; ni++) {
            int r = row0 + wr + mi * 16 + qr;
            int c = col0 + wc + ni * 8 + qc;
            float b0 = bias[c], b1 = bias[c + 1];
            float2 o0 = make_float2(acc[mi][ni][0] + b0, acc[mi][ni][1] + b1);
            float2 o1 = make_float2(acc[mi][ni][2] + b0, acc[mi][ni][3] + b1);
            *(float2*)&C[(size_t)r * N + c] = o0;
            *(float2*)&C[(size_t)(r + 8) * N + c] = o1;
        }
    }
}

// ---------------- RoPE table + RoPE/split ---------------------------------
__global__ __launch_bounds__(256) void rope_table_kernel(float* ct, float* st) {
    int idx = blockIdx.x * 256 + threadIdx.x;   // TT*32 = 65536
    int t = idx >> 5, i = idx & 31;
    double inv = exp(-(double)i / 32.0 * 9.210340371976184);   // ln(10000)
    double sv, cv;
    sincos((double)t * inv, &sv, &cv);
    ct[idx] = (float)cv;
    st[idx] = (float)sv;
}

__global__ __launch_bounds__(256) void rope_split_kernel(
    const float* __restrict__ qkv, const float* __restrict__ ct,
    const float* __restrict__ st,
    float* __restrict__ Q, float* __restrict__ Kh, float* __restrict__ V)
{
    int idx = blockIdx.x * 256 + threadIdx.x;
    int d = idx & 63;
    int t = (idx >> 6) & 2047;
    int h = (idx >> 17) & 15;
    int b = idx >> 21;

    size_t rowoff = ((size_t)b * TT + t) * N_QKV;
    int colq = h * HDD + d;

    float uq = qkv[rowoff + colq];
    float uk = qkv[rowoff + CC + colq];
    float uv = qkv[rowoff + 2 * CC + colq];

    bool hi = d >= 32;
    int i = d & 31;
    float cosv = ct[t * 32 + i];
    float sinv = st[t * 32 + i];

    int pcol = hi ? (colq - 32) : (colq + 32);
    float pq = qkv[rowoff + pcol];
    float pk = qkv[rowoff + CC + pcol];
    float rq = hi ? pq : -pq;
    float rk = hi ? pk : -pk;

    Q[idx]  = uq * cosv + rq * sinv;
    Kh[idx] = uk * cosv + rk * sinv;
    V[idx]  = uv;
}

// ---------------- Flash attention (causal, fp32) ---------------------------
#define QK_LD 72
#define PV_LD 68

__global__ __launch_bounds__(256) void flash_attn_kernel(
    const float* __restrict__ Qg, const float* __restrict__ Kg,
    const float* __restrict__ Vg, float* __restrict__ Yg)
{
    extern __shared__ float sm[];
    float* QsT = sm;
    float* KsT = QsT + 64 * QK_LD;
    float* Vs  = KsT + 64 * QK_LD;
    float* Ps  = Vs  + 64 * PV_LD;

    const int tid = threadIdx.x;
    const int ty = tid >> 4;
    const int tx = tid & 15;
    const int qtile = blockIdx.x;
    const int bh = blockIdx.y;
    const int b = bh >> 4, h = bh & 15;

    const float* Qb = Qg + ((size_t)bh * TT + qtile * 64) * HDD;

    #pragma unroll
    for (int r = 0; r < 4; r++) {
        int idx = tid + r * 256;
        int trow = idx >> 4;
        int dg = (idx & 15) << 2;
        float4 v = *(const float4*)(Qb + trow * 64 + dg);
        QsT[(dg + 0) * QK_LD + trow] = v.x;
        QsT[(dg + 1) * QK_LD + trow] = v.y;
        QsT[(dg + 2) * QK_LD + trow] = v.z;
        QsT[(dg + 3) * QK_LD + trow] = v.w;
    }

    float m[4], l[4], acc[4][4];
    #pragma unroll
    for (int i = 0; i < 4; i++) {
        m[i] = -1e30f; l[i] = 0.f;
        #pragma unroll
        for (int j = 0; j < 4; j++) acc[i][j] = 0.f;
    }
    __syncthreads();

    for (int kt = 0; kt <= qtile; kt++) {
        const float* Kb = Kg + ((size_t)bh * TT + kt * 64) * HDD;
        const float* Vb = Vg + ((size_t)bh * TT + kt * 64) * HDD;
        #pragma unroll
        for (int r = 0; r < 4; r++) {
            int idx = tid + r * 256;
            int trow = idx >> 4;
            int dg = (idx & 15) << 2;
            float4 v = *(const float4*)(Kb + trow * 64 + dg);
            KsT[(dg + 0) * QK_LD + trow] = v.x;
            KsT[(dg + 1) * QK_LD + trow] = v.y;
            KsT[(dg + 2) * QK_LD + trow] = v.z;
            KsT[(dg + 3) * QK_LD + trow] = v.w;
            float4 w = *(const float4*)(Vb + trow * 64 + dg);
            *(float4*)(Vs + trow * PV_LD + dg) = w;
        }
        __syncthreads();

        float s[4][4];
        #pragma unroll
        for (int i = 0; i < 4; i++)
            #pragma unroll
            for (int j = 0; j < 4; j++) s[i][j] = 0.f;

        #pragma unroll 8
        for (int k = 0; k < 64; k++) {
            float4 qv = *(const float4*)(QsT + k * QK_LD + (ty << 2));
            float4 kv = *(const float4*)(KsT + k * QK_LD + (tx << 2));
            s[0][0] += qv.x * kv.x; s[0][1] += qv.x * kv.y; s[0][2] += qv.x * kv.z; s[0][3] += qv.x * kv.w;
            s[1][0] += qv.y * kv.x; s[1][1] += qv.y * kv.y; s[1][2] += qv.y * kv.z; s[1][3] += qv.y * kv.w;
            s[2][0] += qv.z * kv.x; s[2][1] += qv.z * kv.y; s[2][2] += qv.z * kv.z; s[2][3] += qv.z * kv.w;
            s[3][0] += qv.w * kv.x; s[3][1] += qv.w * kv.y; s[3][2] += qv.w * kv.z; s[3][3] += qv.w * kv.w;
        }

        const float sc = 0.125f;
        if (kt == qtile) {
            #pragma unroll
            for (int i = 0; i < 4; i++)
                #pragma unroll
                for (int j = 0; j < 4; j++) {
                    int rr = (ty << 2) + i, cc = (tx << 2) + j;
                    s[i][j] = (cc <= rr) ? s[i][j] * sc : -1e30f;
                }
        } else {
            #pragma unroll
            for (int i = 0; i < 4; i++)
                #pragma unroll
                for (int j = 0; j < 4; j++) s[i][j] *= sc;
        }

        #pragma unroll
        for (int i = 0; i < 4; i++) {
            float mx = fmaxf(fmaxf(s[i][0], s[i][1]), fmaxf(s[i][2], s[i][3]));
            #pragma unroll
            for (int o = 8; o > 0; o >>= 1)
                mx = fmaxf(mx, __shfl_xor_sync(0xffffffffu, mx, o));
            float mnew = fmaxf(m[i], mx);
            float alpha = __expf(m[i] - mnew);
            float rs = 0.f;
            #pragma unroll
            for (int j = 0; j < 4; j++) {
                float p = __expf(s[i][j] - mnew);
                s[i][j] = p;
                rs += p;
            }
            #pragma unroll
            for (int o = 8; o > 0; o >>= 1)
                rs += __shfl_xor_sync(0xffffffffu, rs, o);
            l[i] = l[i] * alpha + rs;
            m[i] = mnew;
            acc[i][0] *= alpha; acc[i][1] *= alpha; acc[i][2] *= alpha; acc[i][3] *= alpha;
        }

        #pragma unroll
        for (int i = 0; i < 4; i++) {
            float4 pv = make_float4(s[i][0], s[i][1], s[i][2], s[i][3]);
            *(float4*)(Ps + (((ty << 2) + i) * PV_LD) + (tx << 2)) = pv;
        }
        __syncthreads();

        #pragma unroll 8
        for (int c = 0; c < 64; c++) {
            float4 vv = *(const float4*)(Vs + c * PV_LD + (tx << 2));
            float p0 = Ps[((ty << 2) + 0) * PV_LD + c];
            float p1 = Ps[((ty << 2) + 1) * PV_LD + c];
            float p2 = Ps[((ty << 2) + 2) * PV_LD + c];
            float p3 = Ps[((ty << 2) + 3) * PV_LD + c];
            acc[0][0] += p0 * vv.x; acc[0][1] += p0 * vv.y; acc[0][2] += p0 * vv.z; acc[0][3] += p0 * vv.w;
            acc[1][0] += p1 * vv.x; acc[1][1] += p1 * vv.y; acc[1][2] += p1 * vv.z; acc[1][3] += p1 * vv.w;
            acc[2][0] += p2 * vv.x; acc[2][1] += p2 * vv.y; acc[2][2] += p2 * vv.z; acc[2][3] += p2 * vv.w;
            acc[3][0] += p3 * vv.x; acc[3][1] += p3 * vv.y; acc[3][2] += p3 * vv.z; acc[3][3] += p3 * vv.w;
        }
        __syncthreads();
    }

    #pragma unroll
    for (int i = 0; i < 4; i++) {
        float inv = 1.f / l[i];
        int tglob = qtile * 64 + (ty << 2) + i;
        float4 o = make_float4(acc[i][0] * inv, acc[i][1] * inv,
                               acc[i][2] * inv, acc[i][3] * inv);
        *(float4*)(Yg + ((size_t)(b * TT + tglob)) * CC + h * HDD + (tx << 2)) = o;
    }
}

// ---------------- launch ---------------------------------------------------
extern "C" void kernel_launch(void* const* d_in, const int* in_sizes, int n_in,
                              void* d_out, int out_size)
{
    const float* x     = (const float*)d_in[0];
    const float* Wqkv  = (const float*)d_in[1];
    const float* bqkv  = (const float*)d_in[2];
    const float* Wproj = (const float*)d_in[3];
    const float* bproj = (const float*)d_in[4];
    float* out = (float*)d_out;

    float *qkv, *Q, *K, *V, *Y, *ct, *st;
    __nv_bfloat16 *xh, *xl, *wqh, *wql, *wph, *wpl, *yh, *yl;
    cudaGetSymbolAddress((void**)&qkv, g_qkv);
    cudaGetSymbolAddress((void**)&Q, g_q);
    cudaGetSymbolAddress((void**)&K, g_k);
    cudaGetSymbolAddress((void**)&V, g_v);
    cudaGetSymbolAddress((void**)&Y, g_y);
    cudaGetSymbolAddress((void**)&ct, g_cost);
    cudaGetSymbolAddress((void**)&st, g_sint);
    cudaGetSymbolAddress((void**)&xh, g_xh);
    cudaGetSymbolAddress((void**)&xl, g_xl);
    cudaGetSymbolAddress((void**)&wqh, g_wqh);
    cudaGetSymbolAddress((void**)&wql, g_wql);
    cudaGetSymbolAddress((void**)&wph, g_wph);
    cudaGetSymbolAddress((void**)&wpl, g_wpl);
    cudaGetSymbolAddress((void**)&yh, g_yh);
    cudaGetSymbolAddress((void**)&yl, g_yl);

    cudaFuncSetAttribute(tc_gemm_kernel,
                         cudaFuncAttributeMaxDynamicSharedMemorySize, GSMEM);

    // conversions
    split_kernel<<<(ROWS * CC) / 256, 256>>>(x, xh, xl, ROWS * CC);
    transpose_split_kernel<<<dim3(CC / 32, N_QKV / 32), 256>>>(Wqkv, wqh, wql, CC, N_QKV);
    transpose_split_kernel<<<dim3(CC / 32, CC / 32), 256>>>(Wproj, wph, wpl, CC, CC);
    rope_table_kernel<<<(TT * 32) / 256, 256>>>(ct, st);

    // 1) QKV GEMM + bias (HMMA split-bf16)
    tc_gemm_kernel<<<dim3(N_QKV / 128, ROWS / 128), 256, GSMEM>>>(
        xh, xl, wqh, wql, bqkv, qkv, N_QKV, CC);

    // 2) RoPE + head split
    rope_split_kernel<<<(BB * NHH * TT * HDD) / 256, 256>>>(qkv, ct, st, Q, K, V);

    // 3) causal flash attention (fp32)
    int smem = (2 * 64 * QK_LD + 2 * 64 * PV_LD) * (int)sizeof(float);
    cudaFuncSetAttribute(flash_attn_kernel,
                         cudaFuncAttributeMaxDynamicSharedMemorySize, smem);
    flash_attn_kernel<<<dim3(TT / 64, BB * NHH), 256, smem>>>(Q, K, V, Y);

    // 4) output projection + bias (HMMA split-bf16)
    split_kernel<<<(ROWS * CC) / 256, 256>>>(Y, yh, yl, ROWS * CC);
    tc_gemm_kernel<<<dim3(CC / 128, ROWS / 128), 256, GSMEM>>>(
        yh, yl, wph, wpl, bproj, out, CC, CC);
}

// round 5
// speedup vs baseline: 4.3403x; 2.3471x over previous
#include <cuda_runtime.h>
#include <cuda_bf16.h>
#include <cuda_fp16.h>
#include <math.h>
#include <stdint.h>

// Problem constants
#define BB 4
#define TT 2048
#define CC 1024
#define NHH 16
#define HDD 64
#define ROWS (BB*TT)          // 8192
#define N_QKV (3*CC)          // 3072

// ---------------- scratch (device globals; no allocation) ----------------
__device__ float g_qkv[(size_t)ROWS * N_QKV];

__device__ __nv_bfloat16 g_xh[(size_t)ROWS * CC];
__device__ __nv_bfloat16 g_xl[(size_t)ROWS * CC];
__device__ __nv_bfloat16 g_wqh[(size_t)N_QKV * CC];   // [N,K] transposed
__device__ __nv_bfloat16 g_wql[(size_t)N_QKV * CC];
__device__ __nv_bfloat16 g_wph[(size_t)CC * CC];
__device__ __nv_bfloat16 g_wpl[(size_t)CC * CC];
__device__ __nv_bfloat16 g_yh[(size_t)ROWS * CC];
__device__ __nv_bfloat16 g_yl[(size_t)ROWS * CC];
__device__ float g_cost[(size_t)TT * 32];
__device__ float g_sint[(size_t)TT * 32];

__device__ __half g_qh[(size_t)BB * NHH * TT * HDD];  // [bh][t][d]
__device__ __half g_kh[(size_t)BB * NHH * TT * HDD];  // [bh][t][d]
__device__ __half g_vt[(size_t)BB * NHH * HDD * TT];  // [bh][d][t]

// ---------------- PTX helpers (arch-baseline only: no tcgen05) ------------
__device__ __forceinline__ uint32_t smem_u32(const void* p) {
    uint32_t a;
    asm("{ .reg .u64 t; cvta.to.shared.u64 t, %1; cvt.u32.u64 %0, t; }" : "=r"(a) : "l"(p));
    return a;
}
__device__ __forceinline__ void cp16(uint32_t saddr, const void* g) {
    asm volatile("cp.async.cg.shared.global [%0], [%1], 16;" :: "r"(saddr), "l"(g));
}
__device__ __forceinline__ void ldsm4(uint32_t* r, uint32_t addr) {
    asm volatile("ldmatrix.sync.aligned.m8n8.x4.shared.b16 {%0,%1,%2,%3}, [%4];"
                 : "=r"(r[0]), "=r"(r[1]), "=r"(r[2]), "=r"(r[3]) : "r"(addr));
}
__device__ __forceinline__ void mma16816(float* c, const uint32_t* a, const uint32_t* b) {
    asm volatile(
        "mma.sync.aligned.m16n8k16.row.col.f32.bf16.bf16.f32 "
        "{%0,%1,%2,%3}, {%4,%5,%6,%7}, {%8,%9}, {%0,%1,%2,%3};"
        : "+f"(c[0]), "+f"(c[1]), "+f"(c[2]), "+f"(c[3])
        : "r"(a[0]), "r"(a[1]), "r"(a[2]), "r"(a[3]), "r"(b[0]), "r"(b[1]));
}
__device__ __forceinline__ void mma16816h(float* c, const uint32_t* a, const uint32_t* b) {
    asm volatile(
        "mma.sync.aligned.m16n8k16.row.col.f32.f16.f16.f32 "
        "{%0,%1,%2,%3}, {%4,%5,%6,%7}, {%8,%9}, {%0,%1,%2,%3};"
        : "+f"(c[0]), "+f"(c[1]), "+f"(c[2]), "+f"(c[3])
        : "r"(a[0]), "r"(a[1]), "r"(a[2]), "r"(a[3]), "r"(b[0]), "r"(b[1]));
}
__device__ __forceinline__ uint32_t packh2(float a, float b) {
    __half2 h = __floats2half2_rn(a, b);
    return *(uint32_t*)&h;
}

// ---------------- precision-split conversions ------------------------------
__global__ __launch_bounds__(256) void split_kernel(
    const float* __restrict__ in, __nv_bfloat16* __restrict__ hi,
    __nv_bfloat16* __restrict__ lo, int n)
{
    int i = blockIdx.x * 256 + threadIdx.x;
    if (i >= n) return;
    float v = in[i];
    __nv_bfloat16 h = __float2bfloat16(v);
    hi[i] = h;
    lo[i] = __float2bfloat16(v - __bfloat162float(h));
}

// W[K,N] f32 -> hi/lo[N,K] bf16 (transpose + split)
__global__ __launch_bounds__(256) void transpose_split_kernel(
    const float* __restrict__ W, __nv_bfloat16* __restrict__ hi,
    __nv_bfloat16* __restrict__ lo, int K, int N)
{
    __shared__ float tile[32][33];
    int k0 = blockIdx.x * 32, n0 = blockIdx.y * 32;
    int tx = threadIdx.x & 31, ty = threadIdx.x >> 5;   // 32x8
    #pragma unroll
    for (int r = 0; r < 4; r++)
        tile[ty + 8 * r][tx] = W[(size_t)(k0 + ty + 8 * r) * N + n0 + tx];
    __syncthreads();
    #pragma unroll
    for (int r = 0; r < 4; r++) {
        float v = tile[tx][ty + 8 * r];
        __nv_bfloat16 h = __float2bfloat16(v);
        size_t o = (size_t)(n0 + ty + 8 * r) * K + k0 + tx;
        hi[o] = h;
        lo[o] = __float2bfloat16(v - __bfloat162float(h));
    }
}

// ---------------- HMMA split-bf16 GEMM (mma.sync) -------------------------
#define TILE_B 16384
#define STAGE_B (4*TILE_B)
#define GSMEM (2*STAGE_B)

__device__ __forceinline__ void load_stage(
    uint32_t base, int kt, int tid, int row0, int col0, int K,
    const __nv_bfloat16* __restrict__ Ah, const __nv_bfloat16* __restrict__ Al,
    const __nv_bfloat16* __restrict__ Bh, const __nv_bfloat16* __restrict__ Bl)
{
    int k0 = kt * 64;
    const __nv_bfloat16* srcs[4] = {Ah, Al, Bh, Bl};
    #pragma unroll
    for (int t = 0; t < 4; t++) {
        int rbase = (t < 2) ? row0 : col0;
        const __nv_bfloat16* s = srcs[t];
        #pragma unroll
        for (int i = 0; i < 4; i++) {
            int lin = i * 256 + tid;
            int r = lin >> 3, c = lin & 7;
            uint32_t off = r * 128 + c * 16;
            uint32_t sw = off ^ ((off >> 3) & 0x70);
            cp16(base + t * TILE_B + sw, s + (size_t)(rbase + r) * K + k0 + c * 8);
        }
    }
    asm volatile("cp.async.commit_group;" ::: "memory");
}

__global__ __launch_bounds__(256, 1) void tc_gemm_kernel(
    const __nv_bfloat16* __restrict__ Ah, const __nv_bfloat16* __restrict__ Al,
    const __nv_bfloat16* __restrict__ Bh, const __nv_bfloat16* __restrict__ Bl,
    const float* __restrict__ bias, float* __restrict__ C, int N, int K)
{
    extern __shared__ char smem[];
    uint32_t sb = smem_u32(smem);
    const int tid = threadIdx.x;
    const int wid = tid >> 5, lane = tid & 31;
    const int wr = (wid & 3) * 32;
    const int wc = (wid >> 2) * 64;
    const int col0 = blockIdx.x * 128;
    const int row0 = blockIdx.y * 128;
    const int NK = K >> 6;

    float acc[2][8][4];
    #pragma unroll
    for (int mi = 0; mi < 2; mi++)
        #pragma unroll
        for (int ni = 0; ni < 8; ni++)
            #pragma unroll
            for (int j = 0; j < 4; j++) acc[mi][ni][j] = 0.f;

    load_stage(sb, 0, tid, row0, col0, K, Ah, Al, Bh, Bl);

    const int grp = lane >> 3, l8 = lane & 7;

    for (int kt = 0; kt < NK; kt++) {
        int s = kt & 1;
        if (kt + 1 < NK) {
            load_stage(sb + (s ^ 1) * STAGE_B, kt + 1, tid, row0, col0, K, Ah, Al, Bh, Bl);
            asm volatile("cp.async.wait_group 1;" ::: "memory");
        } else {
            asm volatile("cp.async.wait_group 0;" ::: "memory");
        }
        __syncthreads();

        uint32_t sbase = sb + s * STAGE_B;
        #pragma unroll
        for (int p = 0; p < 3; p++) {
            uint32_t abase = sbase + ((p == 2) ? TILE_B : 0);
            uint32_t bbase = sbase + ((p == 1) ? 3 * TILE_B : 2 * TILE_B);
            #pragma unroll
            for (int ks = 0; ks < 4; ks++) {
                uint32_t a[2][4], b[8][2];
                #pragma unroll
                for (int mi = 0; mi < 2; mi++) {
                    int row = wr + mi * 16 + (grp & 1) * 8 + l8;
                    int chunk = ks * 2 + (grp >> 1);
                    ldsm4(a[mi], abase + row * 128 + ((chunk ^ (row & 7)) << 4));
                }
                #pragma unroll
                for (int nj = 0; nj < 4; nj++) {
                    int row = wc + nj * 16 + (grp >> 1) * 8 + l8;
                    int chunk = ks * 2 + (grp & 1);
                    uint32_t rr[4];
                    ldsm4(rr, bbase + row * 128 + ((chunk ^ (row & 7)) << 4));
                    b[2 * nj][0] = rr[0]; b[2 * nj][1] = rr[1];
                    b[2 * nj + 1][0] = rr[2]; b[2 * nj + 1][1] = rr[3];
                }
                #pragma unroll
                for (int mi = 0; mi < 2; mi++)
                    #pragma unroll
                    for (int ni = 0; ni < 8; ni++)
                        mma16816(acc[mi][ni], a[mi], b[ni]);
            }
        }
        __syncthreads();
    }

    const int qr = lane >> 2, qc = (lane & 3) * 2;
    #pragma unroll
    for (int mi = 0; mi < 2; mi++) {
        #pragma unroll
        for (int ni = 0; ni < 8; ni++) {
            int r = row0 + wr + mi * 16 + qr;
            int c = col0 + wc + ni * 8 + qc;
            float b0 = bias[c], b1 = bias[c + 1];
            float2 o0 = make_float2(acc[mi][ni][0] + b0, acc[mi][ni][1] + b1);
            float2 o1 = make_float2(acc[mi][ni][2] + b0, acc[mi][ni][3] + b1);
            *(float2*)&C[(size_t)r * N + c] = o0;
            *(float2*)&C[(size_t)(r + 8) * N + c] = o1;
        }
    }
}

// ---------------- RoPE table + RoPE (fp16 out) -----------------------------
__global__ __launch_bounds__(256) void rope_table_kernel(float* ct, float* st) {
    int idx = blockIdx.x * 256 + threadIdx.x;
    int t = idx >> 5, i = idx & 31;
    double inv = exp(-(double)i / 32.0 * 9.210340371976184);
    double sv, cv;
    sincos((double)t * inv, &sv, &cv);
    ct[idx] = (float)cv;
    st[idx] = (float)sv;
}

__global__ __launch_bounds__(256) void rope_half_kernel(
    const float* __restrict__ qkv, const float* __restrict__ ct,
    const float* __restrict__ st,
    __half* __restrict__ Q, __half* __restrict__ Kh)
{
    int idx = blockIdx.x * 256 + threadIdx.x;
    int d = idx & 63;
    int t = (idx >> 6) & 2047;
    int h = (idx >> 17) & 15;
    int b = idx >> 21;

    size_t rowoff = ((size_t)b * TT + t) * N_QKV;
    int colq = h * HDD + d;

    float uq = qkv[rowoff + colq];
    float uk = qkv[rowoff + CC + colq];

    bool hi = d >= 32;
    int i = d & 31;
    float cosv = ct[t * 32 + i];
    float sinv = st[t * 32 + i];

    int pcol = hi ? (colq - 32) : (colq + 32);
    float pq = qkv[rowoff + pcol];
    float pk = qkv[rowoff + CC + pcol];
    float rq = hi ? pq : -pq;
    float rk = hi ? pk : -pk;

    Q[idx]  = __float2half(uq * cosv + rq * sinv);
    Kh[idx] = __float2half(uk * cosv + rk * sinv);
}

// V -> [bh][d][t] fp16 transpose
__global__ __launch_bounds__(256) void vt_kernel(
    const float* __restrict__ qkv, __half* __restrict__ Vt)
{
    __shared__ __half sm[64][72];
    int t0 = blockIdx.x * 64;
    int bh = blockIdx.y;
    int b = bh >> 4, h = bh & 15;
    #pragma unroll
    for (int i = 0; i < 4; i++) {
        int lin = i * 256 + threadIdx.x;     // 1024
        int t = lin >> 4, dc = (lin & 15) * 4;
        float4 v = *(const float4*)&qkv[((size_t)(b * TT + t0 + t)) * N_QKV + 2 * CC + h * 64 + dc];
        sm[dc + 0][t] = __float2half(v.x);
        sm[dc + 1][t] = __float2half(v.y);
        sm[dc + 2][t] = __float2half(v.z);
        sm[dc + 3][t] = __float2half(v.w);
    }
    __syncthreads();
    #pragma unroll
    for (int i = 0; i < 2; i++) {
        int lin = i * 256 + threadIdx.x;     // 512
        int d = lin >> 3, tc = (lin & 7) * 8;
        uint4 o = *(uint4*)&sm[d][tc];
        *(uint4*)&Vt[((size_t)bh * 64 + d) * TT + t0 + tc] = o;
    }
}

// ---------------- Tensor-core flash attention (fp16 mma.sync) --------------
// BM=128, BN=64, 256 threads (8 warps x 16 rows). Emits split-bf16 yh/yl.
#define AT_SMEM (16384 + 2*16384)   // Q + 2 stages of (K 8KB + V 8KB)

__device__ __forceinline__ void attn_load_kv(
    uint32_t dst, const __half* __restrict__ Kb, const __half* __restrict__ Vb,
    int ktbase, int tid)
{
    #pragma unroll
    for (int i = 0; i < 2; i++) {
        int lin = i * 256 + tid;
        int r = lin >> 3, c = lin & 7;
        uint32_t sw = r * 128 + ((c ^ (r & 7)) << 4);
        cp16(dst + sw, Kb + (size_t)(ktbase + r) * HDD + c * 8);
        cp16(dst + 8192 + sw, Vb + (size_t)r * TT + ktbase + c * 8);
    }
    asm volatile("cp.async.commit_group;" ::: "memory");
}

__global__ __launch_bounds__(256, 1) void attn_kernel(
    const __half* __restrict__ Qg, const __half* __restrict__ Kg,
    const __half* __restrict__ Vtg,
    __nv_bfloat16* __restrict__ Yh, __nv_bfloat16* __restrict__ Yl)
{
    extern __shared__ char smem[];
    uint32_t sb = smem_u32(smem);
    uint32_t sQ = sb;
    uint32_t sKV = sb + 16384;

    const int tid = threadIdx.x;
    const int wid = tid >> 5, lane = tid & 31;
    const int grp = lane >> 3, l8 = lane & 7;
    const int qt = (int)gridDim.x - 1 - (int)blockIdx.x;   // longest first
    const int bh = blockIdx.y;
    const int q0 = qt * 128;
    const int nkt = 2 * qt + 2;

    const __half* Qb = Qg + ((size_t)bh * TT + q0) * HDD;
    const __half* Kb = Kg + (size_t)bh * TT * HDD;
    const __half* Vb = Vtg + (size_t)bh * HDD * TT;

    // stage Q (group 0) then prefetch kv tile 0 (group 1)
    #pragma unroll
    for (int i = 0; i < 4; i++) {
        int lin = i * 256 + tid;
        int r = lin >> 3, c = lin & 7;
        cp16(sQ + r * 128 + ((c ^ (r & 7)) << 4), Qb + (size_t)r * HDD + c * 8);
    }
    asm volatile("cp.async.commit_group;" ::: "memory");
    attn_load_kv(sKV, Kb, Vb, 0, tid);

    asm volatile("cp.async.wait_group 1;" ::: "memory");   // Q ready
    __syncthreads();

    // preload Q fragments
    uint32_t qf[4][4];
    #pragma unroll
    for (int kc = 0; kc < 4; kc++) {
        int row = wid * 16 + (grp & 1) * 8 + l8;
        int ch = kc * 2 + (grp >> 1);
        ldsm4(qf[kc], sQ + row * 128 + ((ch ^ (row & 7)) << 4));
    }

    float m0 = -1e30f, m1 = -1e30f, l0 = 0.f, l1 = 0.f;
    float oacc[8][4];
    #pragma unroll
    for (int nj = 0; nj < 8; nj++)
        #pragma unroll
        for (int e = 0; e < 4; e++) oacc[nj][e] = 0.f;

    const int rquad = lane >> 2;       // 0..7
    const int cpair = (lane & 3) * 2;  // 0,2,4,6

    for (int kt = 0; kt < nkt; kt++) {
        int s = kt & 1;
        if (kt + 1 < nkt) {
            attn_load_kv(sKV + (s ^ 1) * 16384, Kb, Vb, (kt + 1) * 64, tid);
            asm volatile("cp.async.wait_group 1;" ::: "memory");
        } else {
            asm volatile("cp.async.wait_group 0;" ::: "memory");
        }
        __syncthreads();

        uint32_t sK = sKV + s * 16384;
        uint32_t sV = sK + 8192;

        // S = Q K^T
        float sacc[8][4];
        #pragma unroll
        for (int nj = 0; nj < 8; nj++)
            #pragma unroll
            for (int e = 0; e < 4; e++) sacc[nj][e] = 0.f;

        #pragma unroll
        for (int ks = 0; ks < 4; ks++) {
            uint32_t b[8][2];
            #pragma unroll
            for (int nj = 0; nj < 4; nj++) {
                int row = nj * 16 + (grp >> 1) * 8 + l8;
                int ch = ks * 2 + (grp & 1);
                uint32_t rr[4];
                ldsm4(rr, sK + row * 128 + ((ch ^ (row & 7)) << 4));
                b[2 * nj][0] = rr[0]; b[2 * nj][1] = rr[1];
                b[2 * nj + 1][0] = rr[2]; b[2 * nj + 1][1] = rr[3];
            }
            #pragma unroll
            for (int nj = 0; nj < 8; nj++)
                mma16816h(sacc[nj], qf[ks], b[nj]);
        }

        // scale + causal mask (only last two tiles touch the diagonal)
        const float sc = 0.125f;
        if (kt >= nkt - 2) {
            int row0g = q0 + wid * 16 + rquad;
            #pragma unroll
            for (int nj = 0; nj < 8; nj++) {
                int colg = kt * 64 + nj * 8 + cpair;
                #pragma unroll
                for (int e = 0; e < 4; e++) {
                    int cg = colg + (e & 1);
                    int rg = row0g + ((e >= 2) ? 8 : 0);
                    sacc[nj][e] = (cg <= rg) ? sacc[nj][e] * sc : -1e30f;
                }
            }
        } else {
            #pragma unroll
            for (int nj = 0; nj < 8; nj++)
                #pragma unroll
                for (int e = 0; e < 4; e++) sacc[nj][e] *= sc;
        }

        // online softmax (two rows per thread; 4-lane quad reductions)
        float rm0 = -1e30f, rm1 = -1e30f;
        #pragma unroll
        for (int nj = 0; nj < 8; nj++) {
            rm0 = fmaxf(rm0, fmaxf(sacc[nj][0], sacc[nj][1]));
            rm1 = fmaxf(rm1, fmaxf(sacc[nj][2], sacc[nj][3]));
        }
        rm0 = fmaxf(rm0, __shfl_xor_sync(0xffffffffu, rm0, 1));
        rm0 = fmaxf(rm0, __shfl_xor_sync(0xffffffffu, rm0, 2));
        rm1 = fmaxf(rm1, __shfl_xor_sync(0xffffffffu, rm1, 1));
        rm1 = fmaxf(rm1, __shfl_xor_sync(0xffffffffu, rm1, 2));

        float n0 = fmaxf(m0, rm0), n1 = fmaxf(m1, rm1);
        float a0 = __expf(m0 - n0), a1 = __expf(m1 - n1);
        float rs0 = 0.f, rs1 = 0.f;
        #pragma unroll
        for (int nj = 0; nj < 8; nj++) {
            sacc[nj][0] = __expf(sacc[nj][0] - n0);
            sacc[nj][1] = __expf(sacc[nj][1] - n0);
            sacc[nj][2] = __expf(sacc[nj][2] - n1);
            sacc[nj][3] = __expf(sacc[nj][3] - n1);
            rs0 += sacc[nj][0] + sacc[nj][1];
            rs1 += sacc[nj][2] + sacc[nj][3];
        }
        rs0 += __shfl_xor_sync(0xffffffffu, rs0, 1);
        rs0 += __shfl_xor_sync(0xffffffffu, rs0, 2);
        rs1 += __shfl_xor_sync(0xffffffffu, rs1, 1);
        rs1 += __shfl_xor_sync(0xffffffffu, rs1, 2);

        l0 = l0 * a0 + rs0;
        l1 = l1 * a1 + rs1;
        m0 = n0; m1 = n1;
        #pragma unroll
        for (int nj = 0; nj < 8; nj++) {
            oacc[nj][0] *= a0; oacc[nj][1] *= a0;
            oacc[nj][2] *= a1; oacc[nj][3] *= a1;
        }

        // pack P into A-operand fragments (registers only)
        uint32_t pf[4][4];
        #pragma unroll
        for (int kc = 0; kc < 4; kc++) {
            pf[kc][0] = packh2(sacc[2 * kc][0],     sacc[2 * kc][1]);
            pf[kc][1] = packh2(sacc[2 * kc][2],     sacc[2 * kc][3]);
            pf[kc][2] = packh2(sacc[2 * kc + 1][0], sacc[2 * kc + 1][1]);
            pf[kc][3] = packh2(sacc[2 * kc + 1][2], sacc[2 * kc + 1][3]);
        }

        // O += P @ V   (V stored [d][t] so same B-frag pattern as K)
        #pragma unroll
        for (int kc = 0; kc < 4; kc++) {
            uint32_t vb[8][2];
            #pragma unroll
            for (int nj = 0; nj < 4; nj++) {
                int row = nj * 16 + (grp >> 1) * 8 + l8;
                int ch = kc * 2 + (grp & 1);
                uint32_t rr[4];
                ldsm4(rr, sV + row * 128 + ((ch ^ (row & 7)) << 4));
                vb[2 * nj][0] = rr[0]; vb[2 * nj][1] = rr[1];
                vb[2 * nj + 1][0] = rr[2]; vb[2 * nj + 1][1] = rr[3];
            }
            #pragma unroll
            for (int nj = 0; nj < 8; nj++)
                mma16816h(oacc[nj], pf[kc], vb[nj]);
        }
        __syncthreads();
    }

    // epilogue: normalize + split-bf16 store to [b,t,c]
    float i0 = 1.f / l0, i1 = 1.f / l1;
    int b_ = bh >> 4, h = bh & 15;
    int r0g = q0 + wid * 16 + rquad;
    #pragma unroll
    for (int nj = 0; nj < 8; nj++) {
        int c = h * 64 + nj * 8 + cpair;
        float v0 = oacc[nj][0] * i0, v1 = oacc[nj][1] * i0;
        float v2 = oacc[nj][2] * i1, v3 = oacc[nj][3] * i1;
        size_t o0 = (size_t)(b_ * TT + r0g) * CC + c;
        size_t o1 = (size_t)(b_ * TT + r0g + 8) * CC + c;
        __nv_bfloat16 h0 = __float2bfloat16(v0), h1 = __float2bfloat16(v1);
        __nv_bfloat16 h2 = __float2bfloat16(v2), h3 = __float2bfloat16(v3);
        *(__nv_bfloat162*)&Yh[o0] = __nv_bfloat162(h0, h1);
        *(__nv_bfloat162*)&Yh[o1] = __nv_bfloat162(h2, h3);
        *(__nv_bfloat162*)&Yl[o0] = __nv_bfloat162(
            __float2bfloat16(v0 - __bfloat162float(h0)),
            __float2bfloat16(v1 - __bfloat162float(h1)));
        *(__nv_bfloat162*)&Yl[o1] = __nv_bfloat162(
            __float2bfloat16(v2 - __bfloat162float(h2)),
            __float2bfloat16(v3 - __bfloat162float(h3)));
    }
}

// ---------------- launch ---------------------------------------------------
extern "C" void kernel_launch(void* const* d_in, const int* in_sizes, int n_in,
                              void* d_out, int out_size)
{
    const float* x     = (const float*)d_in[0];
    const float* Wqkv  = (const float*)d_in[1];
    const float* bqkv  = (const float*)d_in[2];
    const float* Wproj = (const float*)d_in[3];
    const float* bproj = (const float*)d_in[4];
    float* out = (float*)d_out;

    float *qkv, *ct, *st;
    __nv_bfloat16 *xh, *xl, *wqh, *wql, *wph, *wpl, *yh, *yl;
    __half *qh, *kh, *vt;
    cudaGetSymbolAddress((void**)&qkv, g_qkv);
    cudaGetSymbolAddress((void**)&ct, g_cost);
    cudaGetSymbolAddress((void**)&st, g_sint);
    cudaGetSymbolAddress((void**)&xh, g_xh);
    cudaGetSymbolAddress((void**)&xl, g_xl);
    cudaGetSymbolAddress((void**)&wqh, g_wqh);
    cudaGetSymbolAddress((void**)&wql, g_wql);
    cudaGetSymbolAddress((void**)&wph, g_wph);
    cudaGetSymbolAddress((void**)&wpl, g_wpl);
    cudaGetSymbolAddress((void**)&yh, g_yh);
    cudaGetSymbolAddress((void**)&yl, g_yl);
    cudaGetSymbolAddress((void**)&qh, g_qh);
    cudaGetSymbolAddress((void**)&kh, g_kh);
    cudaGetSymbolAddress((void**)&vt, g_vt);

    cudaFuncSetAttribute(tc_gemm_kernel,
                         cudaFuncAttributeMaxDynamicSharedMemorySize, GSMEM);
    cudaFuncSetAttribute(attn_kernel,
                         cudaFuncAttributeMaxDynamicSharedMemorySize, AT_SMEM);

    // conversions
    split_kernel<<<(ROWS * CC) / 256, 256>>>(x, xh, xl, ROWS * CC);
    transpose_split_kernel<<<dim3(CC / 32, N_QKV / 32), 256>>>(Wqkv, wqh, wql, CC, N_QKV);
    transpose_split_kernel<<<dim3(CC / 32, CC / 32), 256>>>(Wproj, wph, wpl, CC, CC);
    rope_table_kernel<<<(TT * 32) / 256, 256>>>(ct, st);

    // 1) QKV GEMM + bias (HMMA split-bf16)
    tc_gemm_kernel<<<dim3(N_QKV / 128, ROWS / 128), 256, GSMEM>>>(
        xh, xl, wqh, wql, bqkv, qkv, N_QKV, CC);

    // 2) RoPE -> fp16 Q,K ; V -> fp16 [bh][d][t]
    rope_half_kernel<<<(BB * NHH * TT * HDD) / 256, 256>>>(qkv, ct, st, qh, kh);
    vt_kernel<<<dim3(TT / 64, BB * NHH), 256>>>(qkv, vt);

    // 3) tensor-core causal flash attention -> split-bf16 Y
    attn_kernel<<<dim3(TT / 128, BB * NHH), 256, AT_SMEM>>>(qh, kh, vt, yh, yl);

    // 4) output projection + bias (HMMA split-bf16)
    tc_gemm_kernel<<<dim3(CC / 128, ROWS / 128), 256, GSMEM>>>(
        yh, yl, wph, wpl, bproj, out, CC, CC);
}